// round 1
// baseline (speedup 1.0000x reference)
#include <cuda_runtime.h>

#define DIMS 2048
#define SEQ  4096

// ---------------- scratch (static device globals; no allocation) ------------
__device__ float        g_A[SEQ * DIMS];   // A = X @ W_hi^T + b
__device__ float        g_h[2][DIMS];      // double-buffered hidden state
__device__ unsigned int g_bar;             // monotonic grid barrier counter

// ---------------- init: reset barrier, seed h0 ------------------------------
__global__ void init_kernel(const float* __restrict__ h0) {
    int i = blockIdx.x * blockDim.x + threadIdx.x;
    if (i < DIMS) g_h[0][i] = h0[i];
    if (i == 0)   g_bar = 0u;
}

// ---------------- phase 1: A = X @ W^T + b  (fp32 tiled GEMM) ----------------
// X: [SEQ, DIMS] row-major, W: [DIMS, DIMS] row-major (both K-contiguous).
#define BM 128
#define BN 128
#define BK 8

__global__ __launch_bounds__(256) void gemm_kernel(
    const float* __restrict__ X, const float* __restrict__ W,
    const float* __restrict__ b, float* __restrict__ A)
{
    __shared__ float Xs[BK][BM];
    __shared__ float Ws[BK][BN];

    const int tid = threadIdx.x;
    const int m0  = blockIdx.y * BM;
    const int n0  = blockIdx.x * BN;
    const int tx  = tid & 15;       // 0..15 -> cols tx + 16*j
    const int ty  = tid >> 4;       // 0..15 -> rows ty + 16*i

    const int lr  = tid >> 1;       // 0..127: tile row loaded by this thread
    const int lk  = (tid & 1) * 4;  // 0 or 4: k-subgroup

    float acc[8][8];
#pragma unroll
    for (int i = 0; i < 8; i++)
#pragma unroll
        for (int j = 0; j < 8; j++) acc[i][j] = 0.f;

    for (int k0 = 0; k0 < DIMS; k0 += BK) {
        float4 xv = *(const float4*)(X + (size_t)(m0 + lr) * DIMS + k0 + lk);
        float4 wv = *(const float4*)(W + (size_t)(n0 + lr) * DIMS + k0 + lk);
        __syncthreads();
        Xs[lk + 0][lr] = xv.x; Xs[lk + 1][lr] = xv.y;
        Xs[lk + 2][lr] = xv.z; Xs[lk + 3][lr] = xv.w;
        Ws[lk + 0][lr] = wv.x; Ws[lk + 1][lr] = wv.y;
        Ws[lk + 2][lr] = wv.z; Ws[lk + 3][lr] = wv.w;
        __syncthreads();
#pragma unroll
        for (int k = 0; k < BK; k++) {
            float xr[8], wr[8];
#pragma unroll
            for (int i = 0; i < 8; i++) xr[i] = Xs[k][ty + 16 * i];
#pragma unroll
            for (int j = 0; j < 8; j++) wr[j] = Ws[k][tx + 16 * j];
#pragma unroll
            for (int i = 0; i < 8; i++)
#pragma unroll
                for (int j = 0; j < 8; j++) acc[i][j] += xr[i] * wr[j];
        }
    }
#pragma unroll
    for (int i = 0; i < 8; i++) {
        const int m = m0 + ty + 16 * i;
#pragma unroll
        for (int j = 0; j < 8; j++) {
            const int n = n0 + tx + 16 * j;
            A[(size_t)m * DIMS + n] = acc[i][j] + b[n];
        }
    }
}

// ---------------- phase 2: persistent sequential RNN -------------------------
// 128 CTAs x 256 threads. CTA c owns rows [16c, 16c+16) of W_hh, held in
// registers (2 rows per warp, 16 float4 per row per lane). Per step:
//   load h (8KB) global->smem, 16 dot products, tanh, write h-next + out,
//   grid barrier (atomic arrive + volatile spin; all 128 CTAs co-resident).
#define NCTA 128
#define RPC  16
#define RNN_THREADS 256

__global__ __launch_bounds__(RNN_THREADS, 1) void rnn_kernel(
    const float* __restrict__ X, const float* __restrict__ Whh,
    float* __restrict__ out)
{
    __shared__ float4 h_s[DIMS / 4];   // 8 KB

    const int tid  = threadIdx.x;
    const int wid  = tid >> 5;
    const int lane = tid & 31;
    const int row0 = blockIdx.x * RPC + wid * 2;
    const int row1 = row0 + 1;

    // Stage this CTA's W_hh slice into registers (fixed for the whole scan).
    float4 w0[16], w1[16];
    {
        const float4* W0 = (const float4*)(Whh + (size_t)row0 * DIMS);
        const float4* W1 = (const float4*)(Whh + (size_t)row1 * DIMS);
#pragma unroll
        for (int k = 0; k < 16; k++) {
            w0[k] = W0[lane + 32 * k];
            w1[k] = W1[lane + 32 * k];
        }
    }

    unsigned int target = 0;

    for (int t = 0; t < SEQ; t++) {
        const int cur = t & 1, nxt = cur ^ 1;

        // Prefetch step-constant operands early (independent of h).
        float a0 = 0.f, a1 = 0.f, xr0 = 0.f, xr1 = 0.f;
        if (lane == 0) {
            a0  = g_A[(size_t)t * DIMS + row0];
            a1  = g_A[(size_t)t * DIMS + row1];
            xr0 = X[(size_t)t * DIMS + row0];
            xr1 = X[(size_t)t * DIMS + row1];
        }

        // Cooperative load of h_prev into smem (2 float4 per thread).
        {
            const float4* hg = (const float4*)g_h[cur];
            h_s[tid]               = hg[tid];
            h_s[tid + RNN_THREADS] = hg[tid + RNN_THREADS];
        }
        __syncthreads();

        // 2 dot products per warp, W in registers, h broadcast from smem.
        float acc0 = 0.f, acc1 = 0.f;
#pragma unroll
        for (int k = 0; k < 16; k++) {
            float4 hv = h_s[lane + 32 * k];
            acc0 += w0[k].x * hv.x + w0[k].y * hv.y + w0[k].z * hv.z + w0[k].w * hv.w;
            acc1 += w1[k].x * hv.x + w1[k].y * hv.y + w1[k].z * hv.z + w1[k].w * hv.w;
        }
#pragma unroll
        for (int o = 16; o > 0; o >>= 1) {
            acc0 += __shfl_xor_sync(0xffffffffu, acc0, o);
            acc1 += __shfl_xor_sync(0xffffffffu, acc1, o);
        }

        if (lane == 0) {
            float h0n = tanhf(a0 + acc0);
            float h1n = tanhf(a1 + acc1);
            g_h[nxt][row0] = h0n;
            g_h[nxt][row1] = h1n;
            out[(size_t)t * DIMS + row0] = xr0 + h0n;
            out[(size_t)t * DIMS + row1] = xr1 + h1n;
            __threadfence();   // release h writes before arriving
        }
        __syncthreads();       // all smem reads of this step done

        // Grid-wide barrier: monotonic counter, target grows by NCTA per step.
        target += NCTA;
        if (tid == 0) {
            atomicAdd(&g_bar, 1u);
            while (*(volatile unsigned int*)&g_bar < target) { }
            __threadfence();   // acquire before next step's h loads
        }
        __syncthreads();
    }
}

// ---------------- launch ------------------------------------------------------
extern "C" void kernel_launch(void* const* d_in, const int* in_sizes, int n_in,
                              void* d_out, int out_size) {
    const float* X    = (const float*)d_in[0];  // [SEQ, DIMS]
    const float* W_hi = (const float*)d_in[1];  // [DIMS, DIMS]
    const float* W_hh = (const float*)d_in[2];  // [DIMS, DIMS]
    const float* b    = (const float*)d_in[3];  // [DIMS]
    const float* h0   = (const float*)d_in[4];  // [DIMS]
    float* out = (float*)d_out;

    float* A;
    cudaGetSymbolAddress((void**)&A, g_A);

    init_kernel<<<(DIMS + 255) / 256, 256>>>(h0);

    dim3 ggrid(DIMS / BN, SEQ / BM);            // (16, 32)
    gemm_kernel<<<ggrid, 256>>>(X, W_hi, b, A);

    rnn_kernel<<<NCTA, RNN_THREADS>>>(X, W_hh, out);
}

// round 2
// speedup vs baseline: 1.0759x; 1.0759x over previous
#include <cuda_runtime.h>

#define DIMS 2048
#define SEQ  4096

// ---------------- scratch (static device globals; no allocation) ------------
__device__ float                      g_A[SEQ * DIMS];   // A = X @ W_hi^T + b
__device__ __align__(16) float        g_h[2][DIMS];      // double-buffered hidden state
__device__ unsigned int               g_bar;             // monotonic grid barrier counter

// ---------------- small asm helpers -----------------------------------------
__device__ __forceinline__ float tanh_fast(float x) {
    float y;
    asm("tanh.approx.f32 %0, %1;" : "=f"(y) : "f"(x));
    return y;
}
__device__ __forceinline__ void red_release_add(unsigned int* p, unsigned int v) {
    asm volatile("red.release.gpu.global.add.u32 [%0], %1;" :: "l"(p), "r"(v) : "memory");
}
__device__ __forceinline__ unsigned int ld_acquire(const unsigned int* p) {
    unsigned int v;
    asm volatile("ld.acquire.gpu.global.u32 %0, [%1];" : "=r"(v) : "l"(p) : "memory");
    return v;
}
// packed fp32x2 fma: d = a*b + d  (2 MACs / instruction; ptxas never auto-emits)
__device__ __forceinline__ void ffma2(unsigned long long& d,
                                      unsigned long long a, unsigned long long b) {
    asm("fma.rn.f32x2 %0, %1, %2, %0;" : "+l"(d) : "l"(a), "l"(b));
}
__device__ __forceinline__ float f32x2_hsum(unsigned long long a, unsigned long long b) {
    unsigned long long s;
    asm("add.rn.f32x2 %0, %1, %2;" : "=l"(s) : "l"(a), "l"(b));
    float2 f = *reinterpret_cast<float2*>(&s);
    return f.x + f.y;
}

// ---------------- init: reset barrier, seed h0 ------------------------------
__global__ void init_kernel(const float* __restrict__ h0) {
    int i = blockIdx.x * blockDim.x + threadIdx.x;
    if (i < DIMS) g_h[0][i] = h0[i];
    if (i == 0)   g_bar = 0u;
}

// ---------------- phase 1: A = X @ W^T + b  (fp32 tiled GEMM) ----------------
#define BM 128
#define BN 128
#define BK 8

__global__ __launch_bounds__(256) void gemm_kernel(
    const float* __restrict__ X, const float* __restrict__ W,
    const float* __restrict__ b, float* __restrict__ A)
{
    __shared__ float Xs[BK][BM];
    __shared__ float Ws[BK][BN];

    const int tid = threadIdx.x;
    const int m0  = blockIdx.y * BM;
    const int n0  = blockIdx.x * BN;
    const int tx  = tid & 15;
    const int ty  = tid >> 4;

    const int lr  = tid >> 1;
    const int lk  = (tid & 1) * 4;

    float acc[8][8];
#pragma unroll
    for (int i = 0; i < 8; i++)
#pragma unroll
        for (int j = 0; j < 8; j++) acc[i][j] = 0.f;

    for (int k0 = 0; k0 < DIMS; k0 += BK) {
        float4 xv = *(const float4*)(X + (size_t)(m0 + lr) * DIMS + k0 + lk);
        float4 wv = *(const float4*)(W + (size_t)(n0 + lr) * DIMS + k0 + lk);
        __syncthreads();
        Xs[lk + 0][lr] = xv.x; Xs[lk + 1][lr] = xv.y;
        Xs[lk + 2][lr] = xv.z; Xs[lk + 3][lr] = xv.w;
        Ws[lk + 0][lr] = wv.x; Ws[lk + 1][lr] = wv.y;
        Ws[lk + 2][lr] = wv.z; Ws[lk + 3][lr] = wv.w;
        __syncthreads();
#pragma unroll
        for (int k = 0; k < BK; k++) {
            float xr[8], wr[8];
#pragma unroll
            for (int i = 0; i < 8; i++) xr[i] = Xs[k][ty + 16 * i];
#pragma unroll
            for (int j = 0; j < 8; j++) wr[j] = Ws[k][tx + 16 * j];
#pragma unroll
            for (int i = 0; i < 8; i++)
#pragma unroll
                for (int j = 0; j < 8; j++) acc[i][j] += xr[i] * wr[j];
        }
    }
#pragma unroll
    for (int i = 0; i < 8; i++) {
        const int m = m0 + ty + 16 * i;
#pragma unroll
        for (int j = 0; j < 8; j++) {
            const int n = n0 + tx + 16 * j;
            A[(size_t)m * DIMS + n] = acc[i][j] + b[n];
        }
    }
}

// ---------------- phase 2: persistent sequential RNN -------------------------
// 128 CTAs x 256 threads, 1 CTA/SM (all co-resident; spin barrier is safe).
// CTA c owns rows [16c, 16c+16) of W_hh in registers (2 rows/warp, packed
// as f32x2 pairs). Per step: all-thread acquire-poll of the step counter,
// cooperative 8KB h load to smem, packed-FMA dot, shfl reduce, MUFU tanh,
// release-RED arrival. No MEMBARs, no post-poll broadcast bar.
#define NCTA 128
#define RPC  16
#define RNN_THREADS 256

__global__ __launch_bounds__(RNN_THREADS, 1) void rnn_kernel(
    const float* __restrict__ X, const float* __restrict__ Whh,
    float* __restrict__ out)
{
    __shared__ ulonglong2 h_s[DIMS / 4];   // 8 KB, fp32 h viewed as f32x2 pairs

    const int tid  = threadIdx.x;
    const int wid  = tid >> 5;
    const int lane = tid & 31;
    const int row0 = blockIdx.x * RPC + wid * 2;
    const int row1 = row0 + 1;

    // Stage this CTA's W_hh slice into registers as packed f32x2 pairs.
    ulonglong2 w0[16], w1[16];
    {
        const ulonglong2* W0 = (const ulonglong2*)(Whh + (size_t)row0 * DIMS);
        const ulonglong2* W1 = (const ulonglong2*)(Whh + (size_t)row1 * DIMS);
#pragma unroll
        for (int k = 0; k < 16; k++) {
            w0[k] = W0[lane + 32 * k];
            w1[k] = W1[lane + 32 * k];
        }
    }

    unsigned int target = 0;

    for (int t = 0; t < SEQ; t++) {
        const int cur = t & 1, nxt = cur ^ 1;

        // Step-constant operands (independent of h); issued before the h chain.
        float a0 = 0.f, a1 = 0.f, xr0 = 0.f, xr1 = 0.f;
        if (lane == 0) {
            a0  = g_A[(size_t)t * DIMS + row0];
            a1  = g_A[(size_t)t * DIMS + row1];
            xr0 = X[(size_t)t * DIMS + row0];
            xr1 = X[(size_t)t * DIMS + row1];
        }

        // Wait for previous step's h to be published (skip for t==0: h0 was
        // seeded by init_kernel before this launch).  All threads poll: the
        // warp-LDG is a single broadcast sector read, and every warp proceeds
        // the moment the counter lands — no intra-CTA broadcast barrier.
        if (t > 0) {
            while (ld_acquire(&g_bar) < target) { }
        }

        // Cooperative load of h_prev into smem (2 x 16B per thread).
        {
            const ulonglong2* hg = (const ulonglong2*)g_h[cur];
            h_s[tid]               = hg[tid];
            h_s[tid + RNN_THREADS] = hg[tid + RNN_THREADS];
        }
        __syncthreads();   // bar A: h_s fully staged

        // 2 dot products per warp; W in registers, h broadcast from smem,
        // packed f32x2 FMA (2 MACs / instruction).
        unsigned long long a0x = 0ull, a0y = 0ull, a1x = 0ull, a1y = 0ull;
#pragma unroll
        for (int k = 0; k < 16; k++) {
            ulonglong2 hv = h_s[lane + 32 * k];
            ffma2(a0x, w0[k].x, hv.x);  ffma2(a0y, w0[k].y, hv.y);
            ffma2(a1x, w1[k].x, hv.x);  ffma2(a1y, w1[k].y, hv.y);
        }
        float acc0 = f32x2_hsum(a0x, a0y);
        float acc1 = f32x2_hsum(a1x, a1y);
#pragma unroll
        for (int o = 16; o > 0; o >>= 1) {
            acc0 += __shfl_xor_sync(0xffffffffu, acc0, o);
            acc1 += __shfl_xor_sync(0xffffffffu, acc1, o);
        }

        if (lane == 0) {
            float h0n = tanh_fast(a0 + acc0);
            float h1n = tanh_fast(a1 + acc1);
            g_h[nxt][row0] = h0n;
            g_h[nxt][row1] = h1n;
            out[(size_t)t * DIMS + row0] = xr0 + h0n;
            out[(size_t)t * DIMS + row1] = xr1 + h1n;
        }
        __syncthreads();   // bar B: all 8 warps' h stores are program-ordered
                           // before tid0's release-RED (bar gives happens-before)

        target += NCTA;
        if (tid == 0) red_release_add(&g_bar, 1u);
    }
}

// ---------------- launch ------------------------------------------------------
extern "C" void kernel_launch(void* const* d_in, const int* in_sizes, int n_in,
                              void* d_out, int out_size) {
    const float* X    = (const float*)d_in[0];  // [SEQ, DIMS]
    const float* W_hi = (const float*)d_in[1];  // [DIMS, DIMS]
    const float* W_hh = (const float*)d_in[2];  // [DIMS, DIMS]
    const float* b    = (const float*)d_in[3];  // [DIMS]
    const float* h0   = (const float*)d_in[4];  // [DIMS]
    float* out = (float*)d_out;

    float* A;
    cudaGetSymbolAddress((void**)&A, g_A);

    init_kernel<<<(DIMS + 255) / 256, 256>>>(h0);

    dim3 ggrid(DIMS / BN, SEQ / BM);            // (16, 32)
    gemm_kernel<<<ggrid, 256>>>(X, W_hi, b, A);

    rnn_kernel<<<NCTA, RNN_THREADS>>>(X, W_hh, out);
}